// round 15
// baseline (speedup 1.0000x reference)
#include <cuda_runtime.h>
#include <cuda_fp16.h>
#include <cstdint>
#include <math.h>

#define NSEQ   320
#define DIM    128
#define HEADS  4
#define DH     64
#define INNER  256
#define MROWS  (NSEQ*NSEQ)   // 102400
#define LOG2E  1.4426950408889634f
#define SCL    (0.125f * LOG2E)

// ---------------- scratch (static device globals; no allocation) -------------
__device__ __half   g_pwh[(size_t)MROWS * DIM];    // pw f16
__device__ __half   g_qkvh[(size_t)MROWS * 768];   // q|k|v f16 (q pre-scaled)
__device__ __half   g_biash[(size_t)HEADS * MROWS];// [h][q][k] * log2e, f16
__device__ __half   g_ao[(size_t)MROWS * INNER];   // attn out f16
__device__ __half   g_wqt[768 * DIM];              // Wqkv^T f16 [n][k]
__device__ __half   g_wot[DIM * INNER];            // Wout^T f16 [n][k]

// ---------------- helpers ------------------------------------------------------
__device__ __forceinline__ uint32_t smem_u32(const void* p) {
    uint32_t a;
    asm("{ .reg .u64 t; cvta.to.shared.u64 t, %1; cvt.u32.u64 %0, t; }"
        : "=r"(a) : "l"(p));
    return a;
}
__device__ __forceinline__ void cpa16(uint32_t dst, const void* src) {
    asm volatile("cp.async.cg.shared.global [%0], [%1], 16;"
                 :: "r"(dst), "l"(src));
}
#define CP_COMMIT() asm volatile("cp.async.commit_group;" ::: "memory")
#define CP_WAIT0()  asm volatile("cp.async.wait_group 0;" ::: "memory")
#define CP_WAIT1()  asm volatile("cp.async.wait_group 1;" ::: "memory")
#define CP_WAIT2()  asm volatile("cp.async.wait_group 2;" ::: "memory")

__device__ __forceinline__ float ex2f(float x) {
    float y; asm("ex2.approx.ftz.f32 %0, %1;" : "=f"(y) : "f"(x)); return y;
}
__device__ __forceinline__ uint32_t pack_h2(float lo, float hi) {
    uint32_t r;
    asm("cvt.rn.f16x2.f32 %0, %1, %2;" : "=r"(r) : "f"(hi), "f"(lo));
    return r;
}
__device__ __forceinline__ void stcs32(uint32_t* p, uint32_t v) {
    asm volatile("st.global.cs.b32 [%0], %1;" :: "l"(p), "r"(v));
}
__device__ __forceinline__ void stcs_f2(float* p, float2 v) {
    asm volatile("st.global.cs.v2.f32 [%0], {%1,%2};"
                 :: "l"(p), "f"(v.x), "f"(v.y));
}
__device__ __forceinline__ void mma_f16(float* c, const uint32_t* a,
                                        uint32_t b0, uint32_t b1) {
    asm volatile(
        "mma.sync.aligned.m16n8k16.row.col.f32.f16.f16.f32 "
        "{%0,%1,%2,%3}, {%4,%5,%6,%7}, {%8,%9}, {%0,%1,%2,%3};"
        : "+f"(c[0]), "+f"(c[1]), "+f"(c[2]), "+f"(c[3])
        : "r"(a[0]), "r"(a[1]), "r"(a[2]), "r"(a[3]), "r"(b0), "r"(b1));
}
__device__ __forceinline__ void ldmx4(uint32_t& r0, uint32_t& r1,
                                      uint32_t& r2, uint32_t& r3, uint32_t addr) {
    asm volatile("ldmatrix.sync.aligned.m8n8.x4.shared.b16 {%0,%1,%2,%3}, [%4];"
                 : "=r"(r0), "=r"(r1), "=r"(r2), "=r"(r3) : "r"(addr));
}
__device__ __forceinline__ void ldmx4t(uint32_t& r0, uint32_t& r1,
                                       uint32_t& r2, uint32_t& r3, uint32_t addr) {
    asm volatile("ldmatrix.sync.aligned.m8n8.x4.trans.shared.b16 {%0,%1,%2,%3}, [%4];"
                 : "=r"(r0), "=r"(r1), "=r"(r2), "=r"(r3) : "r"(addr));
}

// ---------------- fused prep: pw -> f16 copy + pair-bias (f16 direct) ---------
__global__ void __launch_bounds__(256) prep_bias(const float* __restrict__ pw,
                                                 const float* __restrict__ Wb,
                                                 uint32_t* __restrict__ pwh32,
                                                 __half* __restrict__ biash) {
    __shared__ float wb[DIM * HEADS];
    const int tid = threadIdx.x;
    for (int i = tid; i < DIM * HEADS; i += 256) wb[i] = Wb[i];
    __syncthreads();
    const int warp = tid >> 5, lane = tid & 31;
    const int row = blockIdx.x * 8 + warp;
    float4 p = *(const float4*)&pw[(size_t)row * DIM + lane * 4];
    pwh32[(size_t)row * 64 + lane * 2 + 0] = pack_h2(p.x, p.y);
    pwh32[(size_t)row * 64 + lane * 2 + 1] = pack_h2(p.z, p.w);
    float acc[HEADS];
    #pragma unroll
    for (int h = 0; h < HEADS; h++) {
        acc[h] = p.x * wb[(lane * 4 + 0) * HEADS + h]
               + p.y * wb[(lane * 4 + 1) * HEADS + h]
               + p.z * wb[(lane * 4 + 2) * HEADS + h]
               + p.w * wb[(lane * 4 + 3) * HEADS + h];
    }
    #pragma unroll
    for (int off = 16; off > 0; off >>= 1)
        #pragma unroll
        for (int h = 0; h < HEADS; h++)
            acc[h] += __shfl_xor_sync(0xffffffffu, acc[h], off);
    if (lane == 0)
        #pragma unroll
        for (int h = 0; h < HEADS; h++)
            biash[(size_t)h * MROWS + row] = __float2half_rn(acc[h] * LOG2E);
}

__global__ void __launch_bounds__(256) prep_wt(const float* __restrict__ Wqkv,
                                               const float* __restrict__ Wout,
                                               __half* __restrict__ wqt,
                                               __half* __restrict__ wot) {
    int idx = blockIdx.x * 256 + threadIdx.x;
    if (idx < 768 * 128) {
        int n = idx >> 7, k = idx & 127;
        wqt[idx] = __float2half_rn(Wqkv[k * 768 + n]);
    }
    if (idx < 128 * 256) {
        int n = idx >> 8, k = idx & 255;
        wot[idx] = __float2half_rn(Wout[k * 128 + n]);
    }
}

// ================== persistent-A qkv GEMM, 3-stage B, ldmatrix frags ==========
#define QA_ST 68
#define QA_SZ (128 * QA_ST)
#define QB_ST 20
#define QB_SZ (128 * QB_ST)
#define QKV_SMEM_BYTES ((QA_SZ + 3 * QB_SZ) * 4)   // 65536 B

__global__ void __launch_bounds__(256, 2) gemm_qkv(const __half* __restrict__ A,
                                                   const __half* __restrict__ Bt,
                                                   uint32_t* __restrict__ O32) {
    extern __shared__ uint32_t sg[];
    const uint32_t sb = smem_u32(sg);
    const int tid = threadIdx.x;
    const int wid = tid >> 5, lane = tid & 31;
    const int wm = wid & 3, wn = wid >> 2;
    const int lg = lane >> 2, lc = lane & 3;
    const int m0 = blockIdx.x * 128;
    const int arow = lane & 15, acol = ((lane >> 4) & 1) * 4;
    const int krow = ((lane >> 4) & 1) * 8 + (lane & 7);
    const int kcol = ((lane >> 3) & 1) * 4;

    #pragma unroll
    for (int t = 0; t < 8; t++) {
        int idx = tid + t * 256;
        int r = idx >> 4, cc = idx & 15;
        cpa16(sb + (r * QA_ST + cc * 4) * 4, A + (size_t)(m0 + r) * 128 + cc * 8);
    }
    #pragma unroll
    for (int t = 0; t < 2; t++) {
        int idx = tid + t * 256;
        int r = idx >> 2, cc = idx & 3;
        cpa16(sb + (QA_SZ + r * QB_ST + cc * 4) * 4, Bt + (size_t)r * 128 + cc * 8);
    }
    CP_COMMIT();
    #pragma unroll
    for (int t = 0; t < 2; t++) {
        int idx = tid + t * 256;
        int r = idx >> 2, cc = idx & 3;
        cpa16(sb + (QA_SZ + QB_SZ + r * QB_ST + cc * 4) * 4,
              Bt + (size_t)r * 128 + 32 + cc * 8);
    }
    CP_COMMIT();

    float acc[2][8][4];
    #pragma unroll
    for (int a = 0; a < 2; a++)
        #pragma unroll
        for (int b = 0; b < 8; b++)
            #pragma unroll
            for (int c = 0; c < 4; c++) acc[a][b][c] = 0.f;

    for (int j = 0; j < 24; j++) {
        if (j + 1 < 24) CP_WAIT1(); else CP_WAIT0();
        __syncthreads();
        if (j + 2 < 24) {
            const int nb2 = (j + 2) >> 2, kc2 = (j + 2) & 3;
            const uint32_t buf = QA_SZ + (uint32_t)((j + 2) % 3) * QB_SZ;
            #pragma unroll
            for (int t = 0; t < 2; t++) {
                int idx = tid + t * 256;
                int r = idx >> 2, cc = idx & 3;
                cpa16(sb + (buf + r * QB_ST + cc * 4) * 4,
                      Bt + (size_t)(nb2 * 128 + r) * 128 + kc2 * 32 + cc * 8);
            }
            CP_COMMIT();
        }
        const uint32_t bbase = sb + (QA_SZ + (uint32_t)(j % 3) * QB_SZ) * 4;
        const int kc = j & 3;
        #pragma unroll
        for (int s = 0; s < 2; s++) {
            const int ka = (kc * 2 + s) * 8;
            uint32_t af[2][4];
            #pragma unroll
            for (int tm = 0; tm < 2; tm++)
                ldmx4(af[tm][0], af[tm][1], af[tm][2], af[tm][3],
                      sb + ((wm * 32 + tm * 16 + arow) * QA_ST + ka + acol) * 4);
            #pragma unroll
            for (int tn2 = 0; tn2 < 4; tn2++) {
                uint32_t b0, b1, b2, b3;
                ldmx4(b0, b1, b2, b3,
                      bbase + ((wn * 64 + 16 * tn2 + krow) * QB_ST + s * 8 + kcol) * 4);
                mma_f16(acc[0][2 * tn2],     af[0], b0, b1);
                mma_f16(acc[0][2 * tn2 + 1], af[0], b2, b3);
                mma_f16(acc[1][2 * tn2],     af[1], b0, b1);
                mma_f16(acc[1][2 * tn2 + 1], af[1], b2, b3);
            }
        }
        if (kc == 3) {
            const int n0 = (j >> 2) * 128;
            #pragma unroll
            for (int tm = 0; tm < 2; tm++) {
                const int r = m0 + wm * 32 + tm * 16 + lg;
                #pragma unroll
                for (int tn = 0; tn < 8; tn++) {
                    const int cc = n0 + wn * 64 + tn * 8 + 2 * lc;
                    const float s = (cc < 256) ? SCL : 1.f;
                    stcs32(&O32[(size_t)r * 384 + (cc >> 1)],
                           pack_h2(acc[tm][tn][0] * s, acc[tm][tn][1] * s));
                    stcs32(&O32[(size_t)(r + 8) * 384 + (cc >> 1)],
                           pack_h2(acc[tm][tn][2] * s, acc[tm][tn][3] * s));
                    acc[tm][tn][0] = 0.f; acc[tm][tn][1] = 0.f;
                    acc[tm][tn][2] = 0.f; acc[tm][tn][3] = 0.f;
                }
            }
        }
    }
}

// ================== out-proj GEMM, 3-stage, ldmatrix frags =====================
#define G_ST  20
#define G_BUF (128 * G_ST)
#define GEMM_SMEM_BYTES (6 * G_BUF * 4)

__global__ void __launch_bounds__(256, 2) gemm_out(const __half* __restrict__ A,
                                                   const __half* __restrict__ Bt,
                                                   const float* __restrict__ bias,
                                                   float* __restrict__ C) {
    extern __shared__ uint32_t sg[];
    const uint32_t sb = smem_u32(sg);
    const int tid = threadIdx.x;
    const int wid = tid >> 5, lane = tid & 31;
    const int wm = wid & 3, wn = wid >> 2;
    const int lg = lane >> 2, lc = lane & 3;
    const int m0 = blockIdx.y * 128;
    const int Ktot = 256, Ntot = 128;
    const int nt = 8;
    const int arow = lane & 15, acol = ((lane >> 4) & 1) * 4;
    const int krow = ((lane >> 4) & 1) * 8 + (lane & 7);
    const int kcol = ((lane >> 3) & 1) * 4;

    float acc[2][8][4];
    #pragma unroll
    for (int a = 0; a < 2; a++)
        #pragma unroll
        for (int b = 0; b < 8; b++)
            #pragma unroll
            for (int c = 0; c < 4; c++) acc[a][b][c] = 0.f;

    #pragma unroll
    for (int st = 0; st < 2; st++) {
        const int kt = st * 32;
        #pragma unroll
        for (int t = 0; t < 2; t++) {
            int idx = tid + t * 256;
            int r = idx >> 2, cc = idx & 3;
            cpa16(sb + ((uint32_t)st * G_BUF + r * G_ST + cc * 4) * 4,
                  A + (size_t)(m0 + r) * Ktot + kt + cc * 8);
        }
        #pragma unroll
        for (int t = 0; t < 2; t++) {
            int idx = tid + t * 256;
            int r = idx >> 2, cc = idx & 3;
            cpa16(sb + ((uint32_t)(3 + st) * G_BUF + r * G_ST + cc * 4) * 4,
                  Bt + (size_t)r * Ktot + kt + cc * 8);
        }
        CP_COMMIT();
    }

    for (int j = 0; j < nt; j++) {
        if (j + 1 < nt) CP_WAIT1(); else CP_WAIT0();
        __syncthreads();
        if (j + 2 < nt) {
            const int st = (j + 2) % 3;
            const int kt = (j + 2) << 5;
            #pragma unroll
            for (int t = 0; t < 2; t++) {
                int idx = tid + t * 256;
                int r = idx >> 2, cc = idx & 3;
                cpa16(sb + ((uint32_t)st * G_BUF + r * G_ST + cc * 4) * 4,
                      A + (size_t)(m0 + r) * Ktot + kt + cc * 8);
            }
            #pragma unroll
            for (int t = 0; t < 2; t++) {
                int idx = tid + t * 256;
                int r = idx >> 2, cc = idx & 3;
                cpa16(sb + ((uint32_t)(3 + st) * G_BUF + r * G_ST + cc * 4) * 4,
                      Bt + (size_t)r * Ktot + kt + cc * 8);
            }
            CP_COMMIT();
        }
        const uint32_t abase = sb + (uint32_t)(j % 3) * G_BUF * 4;
        const uint32_t bbase = sb + (uint32_t)(3 + (j % 3)) * G_BUF * 4;
        #pragma unroll
        for (int s = 0; s < 2; s++) {
            uint32_t af[2][4];
            #pragma unroll
            for (int tm = 0; tm < 2; tm++)
                ldmx4(af[tm][0], af[tm][1], af[tm][2], af[tm][3],
                      abase + ((wm * 32 + tm * 16 + arow) * G_ST + s * 8 + acol) * 4);
            #pragma unroll
            for (int tn2 = 0; tn2 < 4; tn2++) {
                uint32_t b0, b1, b2, b3;
                ldmx4(b0, b1, b2, b3,
                      bbase + ((wn * 64 + 16 * tn2 + krow) * G_ST + s * 8 + kcol) * 4);
                mma_f16(acc[0][2 * tn2],     af[0], b0, b1);
                mma_f16(acc[0][2 * tn2 + 1], af[0], b2, b3);
                mma_f16(acc[1][2 * tn2],     af[1], b0, b1);
                mma_f16(acc[1][2 * tn2 + 1], af[1], b2, b3);
            }
        }
    }
    #pragma unroll
    for (int tm = 0; tm < 2; tm++) {
        const int r = m0 + wm * 32 + tm * 16 + lg;
        #pragma unroll
        for (int tn = 0; tn < 8; tn++) {
            const int cc = wn * 64 + tn * 8 + 2 * lc;
            const float bx = bias[cc], by = bias[cc + 1];
            stcs_f2(&C[(size_t)r * Ntot + cc],
                    make_float2(acc[tm][tn][0] + bx, acc[tm][tn][1] + by));
            stcs_f2(&C[(size_t)(r + 8) * Ntot + cc],
                    make_float2(acc[tm][tn][2] + bx, acc[tm][tn][3] + by));
        }
    }
}

// ================== flash attention: 128 thr, 4 warps over all 4 SMSPs ========
// Warp (mhalf, khalf): q-rows mhalf*32..+31, keys khalf*32..+31 of each chunk.
// Preserves 32-row m-tiles (frag reuse) while using all SM sub-partitions.
// Final: khalf=1 spills partial O + row sums to smem; khalf=0 merges & stores.
#define T_ST  36
#define T_BUF (64 * T_ST)
#define OFF_K  0
#define OFF_V  (3 * T_BUF)
#define ATTN_SMEM_BYTES (6 * T_BUF * 4)   // 55296 B
#define RED_ST 66

__global__ void __launch_bounds__(128, 2) attn_flash(const __half* __restrict__ qkv,
                                                     const uint32_t* __restrict__ bias16,
                                                     uint32_t* __restrict__ ao32) {
    extern __shared__ uint32_t smu[];
    const uint32_t sbm = smem_u32(smu);

    const int qt = blockIdx.x, h = blockIdx.y, i = blockIdx.z;
    const int tid = threadIdx.x;
    const int w = tid >> 5, lane = tid & 31;
    const int lg = lane >> 2, lc = lane & 3;
    const int mhalf = w & 1, khalf = w >> 1;
    const int qg0 = qt * 64;
    const int qr0 = mhalf * 32;
    const int kb = khalf * 32;
    const size_t rowbase = (size_t)i * NSEQ;

    const int krow = ((lane >> 4) & 1) * 8 + (lane & 7);
    const int kcol = ((lane >> 3) & 1) * 4;
    const int vrow = ((lane >> 3) & 1) * 8 + (lane & 7);
    const int vcol = ((lane >> 4) & 1) * 4;

    // ---- prologue: G0 = Q (staged in K2); G1 = ch0; G2 = ch1 ----
    const uint32_t QSTAGE = OFF_K + 2 * T_BUF;
    #pragma unroll
    for (int t = 0; t < 4; t++) {
        int idx = tid + t * 128;
        int r = idx >> 3, cc = idx & 7;
        cpa16(sbm + (QSTAGE + r * T_ST + cc * 4) * 4,
              qkv + (rowbase + qg0 + r) * 768 + h * 64 + cc * 8);
    }
    CP_COMMIT();
    #pragma unroll
    for (int c = 0; c < 2; c++) {
        #pragma unroll
        for (int t = 0; t < 4; t++) {
            int idx = tid + t * 128;
            int r = idx >> 3, cc = idx & 7;
            cpa16(sbm + (OFF_K + c * T_BUF + r * T_ST + cc * 4) * 4,
                  qkv + (rowbase + c * 64 + r) * 768 + 256 + h * 64 + cc * 8);
        }
        #pragma unroll
        for (int t = 0; t < 4; t++) {
            int idx = tid + t * 128;
            int r = idx >> 3, cc = idx & 7;
            cpa16(sbm + (OFF_V + c * T_BUF + r * T_ST + cc * 4) * 4,
                  qkv + (rowbase + c * 64 + r) * 768 + 512 + h * 64 + cc * 8);
        }
        CP_COMMIT();
    }

    // ---- Q -> registers (from K2 region); kc=0 loop-top sync fences reuse ----
    CP_WAIT2();
    __syncthreads();
    const uint32_t* Qst = smu + QSTAGE;
    uint32_t qa[2][4][4];
    #pragma unroll
    for (int mt = 0; mt < 2; mt++) {
        const int qr = qr0 + mt * 16 + lg;
        #pragma unroll
        for (int s = 0; s < 4; s++) {
            qa[mt][s][0] = Qst[qr * T_ST + s * 8 + lc];
            qa[mt][s][1] = Qst[(qr + 8) * T_ST + s * 8 + lc];
            qa[mt][s][2] = Qst[qr * T_ST + s * 8 + lc + 4];
            qa[mt][s][3] = Qst[(qr + 8) * T_ST + s * 8 + lc + 4];
        }
    }

    float oacc[2][8][4];
    #pragma unroll
    for (int mt = 0; mt < 2; mt++)
        #pragma unroll
        for (int a = 0; a < 8; a++)
            #pragma unroll
            for (int b = 0; b < 4; b++) oacc[mt][a][b] = 0.f;
    float ls[2][2] = {{0.f, 0.f}, {0.f, 0.f}};

    for (int kc = 0; kc < 5; kc++) {
        if (kc == 4) CP_WAIT0(); else CP_WAIT1();
        __syncthreads();   // chunk kc resident; fences Q extraction vs K2 reuse

        if (kc < 3) {      // prefetch chunk kc+2 (distance-2)
            const int nb = (kc + 2) % 3;
            const size_t src = rowbase + (size_t)(kc + 2) * 64;
            #pragma unroll
            for (int t = 0; t < 4; t++) {
                int idx = tid + t * 128;
                int r = idx >> 3, cc = idx & 7;
                cpa16(sbm + (OFF_K + nb * T_BUF + r * T_ST + cc * 4) * 4,
                      qkv + (src + r) * 768 + 256 + h * 64 + cc * 8);
            }
            #pragma unroll
            for (int t = 0; t < 4; t++) {
                int idx = tid + t * 128;
                int r = idx >> 3, cc = idx & 7;
                cpa16(sbm + (OFF_V + nb * T_BUF + r * T_ST + cc * 4) * 4,
                      qkv + (src + r) * 768 + 512 + h * 64 + cc * 8);
            }
            CP_COMMIT();
        }

        // bias (f16, *log2e) -> sacc init for this warp's 32 keys
        float sacc[2][4][4];
        #pragma unroll
        for (int mt = 0; mt < 2; mt++) {
            const uint32_t* bp = &bias16[((size_t)h * MROWS
                                  + (size_t)(qg0 + qr0 + mt * 16 + lg) * NSEQ
                                  + kc * 64 + kb) >> 1];
            #pragma unroll
            for (int tn = 0; tn < 4; tn++) {
                uint32_t u0 = bp[tn * 4 + lc];
                uint32_t u1 = bp[(8 * NSEQ >> 1) + tn * 4 + lc];
                float2 b0 = __half22float2(*(const __half2*)&u0);
                float2 b1 = __half22float2(*(const __half2*)&u1);
                sacc[mt][tn][0] = b0.x; sacc[mt][tn][1] = b0.y;
                sacc[mt][tn][2] = b1.x; sacc[mt][tn][3] = b1.y;
            }
        }

        // S = bias + Q @ K^T over this warp's 32 keys
        const uint32_t kbase = sbm + (OFF_K + (kc % 3) * T_BUF) * 4;
        #pragma unroll
        for (int s = 0; s < 4; s++) {
            #pragma unroll
            for (int tn2 = 0; tn2 < 2; tn2++) {
                uint32_t b0, b1, b2, b3;
                ldmx4(b0, b1, b2, b3,
                      kbase + ((kb + 16 * tn2 + krow) * T_ST + 8 * s + kcol) * 4);
                mma_f16(sacc[0][2 * tn2],     qa[0][s], b0, b1);
                mma_f16(sacc[0][2 * tn2 + 1], qa[0][s], b2, b3);
                mma_f16(sacc[1][2 * tn2],     qa[1][s], b0, b1);
                mma_f16(sacc[1][2 * tn2 + 1], qa[1][s], b2, b3);
            }
        }

        // p = 2^s ; pack f16x2 A-frags
        uint32_t ph[2][4][2];
        #pragma unroll
        for (int mt = 0; mt < 2; mt++) {
            #pragma unroll
            for (int tn = 0; tn < 4; tn++) {
                float p0 = ex2f(sacc[mt][tn][0]);
                float p1 = ex2f(sacc[mt][tn][1]);
                float p2 = ex2f(sacc[mt][tn][2]);
                float p3 = ex2f(sacc[mt][tn][3]);
                ls[mt][0] += p0 + p1; ls[mt][1] += p2 + p3;
                ph[mt][tn][0] = pack_h2(p0, p1);
                ph[mt][tn][1] = pack_h2(p2, p3);
            }
        }

        // O += P @ V over this warp's 32 keys
        const uint32_t vbase = sbm + (OFF_V + (kc % 3) * T_BUF) * 4;
        #pragma unroll
        for (int jt = 0; jt < 2; jt++) {
            uint32_t af0[4], af1[4];
            af0[0] = ph[0][2 * jt][0]; af0[1] = ph[0][2 * jt][1];
            af0[2] = ph[0][2 * jt + 1][0]; af0[3] = ph[0][2 * jt + 1][1];
            af1[0] = ph[1][2 * jt][0]; af1[1] = ph[1][2 * jt][1];
            af1[2] = ph[1][2 * jt + 1][0]; af1[3] = ph[1][2 * jt + 1][1];
            #pragma unroll
            for (int tn2 = 0; tn2 < 4; tn2++) {
                uint32_t b0, b1, b2, b3;
                ldmx4t(b0, b1, b2, b3,
                       vbase + ((kb + 16 * jt + vrow) * T_ST + 8 * tn2 + vcol) * 4);
                mma_f16(oacc[0][2 * tn2],     af0, b0, b1);
                mma_f16(oacc[0][2 * tn2 + 1], af0, b2, b3);
                mma_f16(oacc[1][2 * tn2],     af1, b0, b1);
                mma_f16(oacc[1][2 * tn2 + 1], af1, b2, b3);
            }
        }
    }

    // ---- cross-khalf reduction via smem (K buffers done; reuse) ----
    #pragma unroll
    for (int mt = 0; mt < 2; mt++) {
        ls[mt][0] += __shfl_xor_sync(0xffffffffu, ls[mt][0], 1);
        ls[mt][0] += __shfl_xor_sync(0xffffffffu, ls[mt][0], 2);
        ls[mt][1] += __shfl_xor_sync(0xffffffffu, ls[mt][1], 1);
        ls[mt][1] += __shfl_xor_sync(0xffffffffu, ls[mt][1], 2);
    }
    __syncthreads();
    float* Rf = (float*)smu;                 // 64 x RED_ST partial O
    float* Lf = Rf + 64 * RED_ST;            // 64 partial row-sums
    if (khalf == 1) {
        #pragma unroll
        for (int mt = 0; mt < 2; mt++) {
            const int r0 = qr0 + mt * 16 + lg;
            #pragma unroll
            for (int tn = 0; tn < 8; tn++) {
                const int col = tn * 8 + 2 * lc;
                *(float2*)&Rf[r0 * RED_ST + col] =
                    make_float2(oacc[mt][tn][0], oacc[mt][tn][1]);
                *(float2*)&Rf[(r0 + 8) * RED_ST + col] =
                    make_float2(oacc[mt][tn][2], oacc[mt][tn][3]);
            }
            if (lc == 0) { Lf[r0] = ls[mt][0]; Lf[r0 + 8] = ls[mt][1]; }
        }
    }
    __syncthreads();
    if (khalf == 0) {
        #pragma unroll
        for (int mt = 0; mt < 2; mt++) {
            const int r0 = qr0 + mt * 16 + lg;
            const float i0 = 1.f / (ls[mt][0] + Lf[r0]);
            const float i1 = 1.f / (ls[mt][1] + Lf[r0 + 8]);
            #pragma unroll
            for (int tn = 0; tn < 8; tn++) {
                const int col = tn * 8 + 2 * lc;
                float2 a = *(float2*)&Rf[r0 * RED_ST + col];
                float2 b = *(float2*)&Rf[(r0 + 8) * RED_ST + col];
                const int gcol = h * 64 + col;
                stcs32(&ao32[(rowbase + qg0 + r0) * 128 + (gcol >> 1)],
                       pack_h2((oacc[mt][tn][0] + a.x) * i0,
                               (oacc[mt][tn][1] + a.y) * i0));
                stcs32(&ao32[(rowbase + qg0 + r0 + 8) * 128 + (gcol >> 1)],
                       pack_h2((oacc[mt][tn][2] + b.x) * i1,
                               (oacc[mt][tn][3] + b.y) * i1));
            }
        }
    }
}

// ---------------- launch ------------------------------------------------------
extern "C" void kernel_launch(void* const* d_in, const int* in_sizes, int n_in,
                              void* d_out, int out_size) {
    const float* pw    = (const float*)d_in[0];
    const float* Wqkv  = (const float*)d_in[1];
    const float* Wout  = (const float*)d_in[2];
    const float* bout  = (const float*)d_in[3];
    const float* Wbias = (const float*)d_in[4];
    float* out = (float*)d_out;

    __half *pwh, *qkvh, *ao, *wqt, *wot, *biash;
    cudaGetSymbolAddress((void**)&pwh, g_pwh);
    cudaGetSymbolAddress((void**)&qkvh, g_qkvh);
    cudaGetSymbolAddress((void**)&ao, g_ao);
    cudaGetSymbolAddress((void**)&wqt, g_wqt);
    cudaGetSymbolAddress((void**)&wot, g_wot);
    cudaGetSymbolAddress((void**)&biash, g_biash);

    cudaFuncSetAttribute(gemm_qkv,
                         cudaFuncAttributeMaxDynamicSharedMemorySize, QKV_SMEM_BYTES);
    cudaFuncSetAttribute(gemm_out,
                         cudaFuncAttributeMaxDynamicSharedMemorySize, GEMM_SMEM_BYTES);
    cudaFuncSetAttribute(attn_flash,
                         cudaFuncAttributeMaxDynamicSharedMemorySize, ATTN_SMEM_BYTES);

    // 0) weights -> transposed f16
    prep_wt<<<384, 256>>>(Wqkv, Wout, wqt, wot);
    // 1) fused: pw -> f16 + pair bias (f16 direct)
    prep_bias<<<MROWS / 8, 256>>>(pw, Wbias, (uint32_t*)pwh, biash);
    // 2) persistent-A qkv projection (3-stage, ldmatrix)
    gemm_qkv<<<800, 256, QKV_SMEM_BYTES>>>(pwh, wqt, (uint32_t*)qkvh);
    // 3) flash attention: 4 warps (2 m-halves x 2 k-halves), all SMSPs active
    attn_flash<<<dim3(5, HEADS, NSEQ), 128, ATTN_SMEM_BYTES>>>(
        qkvh, (const uint32_t*)biash, (uint32_t*)ao);
    // 4) out = attnout @ Wout + bout (3-stage, ldmatrix)
    gemm_out<<<dim3(1, MROWS / 128), 256, GEMM_SMEM_BYTES>>>(ao, wot, bout, out);
}

// round 16
// speedup vs baseline: 1.1931x; 1.1931x over previous
#include <cuda_runtime.h>
#include <cuda_fp16.h>
#include <cstdint>
#include <math.h>

#define NSEQ   320
#define DIM    128
#define HEADS  4
#define DH     64
#define INNER  256
#define MROWS  (NSEQ*NSEQ)   // 102400
#define LOG2E  1.4426950408889634f
#define SCL    (0.125f * LOG2E)

// ---------------- scratch (static device globals; no allocation) -------------
__device__ __half   g_pwh[(size_t)MROWS * DIM];    // pw f16
__device__ __half   g_qkvh[(size_t)MROWS * 768];   // q|k|v f16 (q pre-scaled)
__device__ __half   g_biash[(size_t)HEADS * MROWS];// [h][q][k] * log2e, f16
__device__ __half   g_ao[(size_t)MROWS * INNER];   // attn out f16
__device__ __half   g_wqt[768 * DIM];              // Wqkv^T f16 [n][k]
__device__ __half   g_wot[DIM * INNER];            // Wout^T f16 [n][k]

// ---------------- helpers ------------------------------------------------------
__device__ __forceinline__ uint32_t smem_u32(const void* p) {
    uint32_t a;
    asm("{ .reg .u64 t; cvta.to.shared.u64 t, %1; cvt.u32.u64 %0, t; }"
        : "=r"(a) : "l"(p));
    return a;
}
__device__ __forceinline__ void cpa16(uint32_t dst, const void* src) {
    asm volatile("cp.async.cg.shared.global [%0], [%1], 16;"
                 :: "r"(dst), "l"(src));
}
#define CP_COMMIT() asm volatile("cp.async.commit_group;" ::: "memory")
#define CP_WAIT0()  asm volatile("cp.async.wait_group 0;" ::: "memory")
#define CP_WAIT1()  asm volatile("cp.async.wait_group 1;" ::: "memory")
#define CP_WAIT2()  asm volatile("cp.async.wait_group 2;" ::: "memory")

__device__ __forceinline__ float ex2f(float x) {
    float y; asm("ex2.approx.ftz.f32 %0, %1;" : "=f"(y) : "f"(x)); return y;
}
__device__ __forceinline__ uint32_t pack_h2(float lo, float hi) {
    uint32_t r;
    asm("cvt.rn.f16x2.f32 %0, %1, %2;" : "=r"(r) : "f"(hi), "f"(lo));
    return r;
}
__device__ __forceinline__ void stcs32(uint32_t* p, uint32_t v) {
    asm volatile("st.global.cs.b32 [%0], %1;" :: "l"(p), "r"(v));
}
__device__ __forceinline__ void stcs_f2(float* p, float2 v) {
    asm volatile("st.global.cs.v2.f32 [%0], {%1,%2};"
                 :: "l"(p), "f"(v.x), "f"(v.y));
}
__device__ __forceinline__ void mma_f16(float* c, const uint32_t* a,
                                        uint32_t b0, uint32_t b1) {
    asm volatile(
        "mma.sync.aligned.m16n8k16.row.col.f32.f16.f16.f32 "
        "{%0,%1,%2,%3}, {%4,%5,%6,%7}, {%8,%9}, {%0,%1,%2,%3};"
        : "+f"(c[0]), "+f"(c[1]), "+f"(c[2]), "+f"(c[3])
        : "r"(a[0]), "r"(a[1]), "r"(a[2]), "r"(a[3]), "r"(b0), "r"(b1));
}
__device__ __forceinline__ void ldmx4(uint32_t& r0, uint32_t& r1,
                                      uint32_t& r2, uint32_t& r3, uint32_t addr) {
    asm volatile("ldmatrix.sync.aligned.m8n8.x4.shared.b16 {%0,%1,%2,%3}, [%4];"
                 : "=r"(r0), "=r"(r1), "=r"(r2), "=r"(r3) : "r"(addr));
}
__device__ __forceinline__ void ldmx4t(uint32_t& r0, uint32_t& r1,
                                       uint32_t& r2, uint32_t& r3, uint32_t addr) {
    asm volatile("ldmatrix.sync.aligned.m8n8.x4.trans.shared.b16 {%0,%1,%2,%3}, [%4];"
                 : "=r"(r0), "=r"(r1), "=r"(r2), "=r"(r3) : "r"(addr));
}

// ---------------- fused prep: pw -> f16 copy + pair-bias (f16 direct) ---------
__global__ void __launch_bounds__(256) prep_bias(const float* __restrict__ pw,
                                                 const float* __restrict__ Wb,
                                                 uint32_t* __restrict__ pwh32,
                                                 __half* __restrict__ biash) {
    __shared__ float wb[DIM * HEADS];
    const int tid = threadIdx.x;
    for (int i = tid; i < DIM * HEADS; i += 256) wb[i] = Wb[i];
    __syncthreads();
    const int warp = tid >> 5, lane = tid & 31;
    const int row = blockIdx.x * 8 + warp;
    float4 p = *(const float4*)&pw[(size_t)row * DIM + lane * 4];
    pwh32[(size_t)row * 64 + lane * 2 + 0] = pack_h2(p.x, p.y);
    pwh32[(size_t)row * 64 + lane * 2 + 1] = pack_h2(p.z, p.w);
    float acc[HEADS];
    #pragma unroll
    for (int h = 0; h < HEADS; h++) {
        acc[h] = p.x * wb[(lane * 4 + 0) * HEADS + h]
               + p.y * wb[(lane * 4 + 1) * HEADS + h]
               + p.z * wb[(lane * 4 + 2) * HEADS + h]
               + p.w * wb[(lane * 4 + 3) * HEADS + h];
    }
    #pragma unroll
    for (int off = 16; off > 0; off >>= 1)
        #pragma unroll
        for (int h = 0; h < HEADS; h++)
            acc[h] += __shfl_xor_sync(0xffffffffu, acc[h], off);
    if (lane == 0)
        #pragma unroll
        for (int h = 0; h < HEADS; h++)
            biash[(size_t)h * MROWS + row] = __float2half_rn(acc[h] * LOG2E);
}

__global__ void __launch_bounds__(256) prep_wt(const float* __restrict__ Wqkv,
                                               const float* __restrict__ Wout,
                                               __half* __restrict__ wqt,
                                               __half* __restrict__ wot) {
    int idx = blockIdx.x * 256 + threadIdx.x;
    if (idx < 768 * 128) {
        int n = idx >> 7, k = idx & 127;
        wqt[idx] = __float2half_rn(Wqkv[k * 768 + n]);
    }
    if (idx < 128 * 256) {
        int n = idx >> 8, k = idx & 255;
        wot[idx] = __float2half_rn(Wout[k * 128 + n]);
    }
}

// ================== persistent-A qkv GEMM: BK=64, 3-stage B, ldmatrix =========
// 12 iterations (6 n-blocks x 2 k-chunks of 64). Half the barriers of BK=32.
#define QA_ST 68
#define QA_SZ (128 * QA_ST)          // 8704 u32
#define QB_ST 36
#define QB_SZ (128 * QB_ST)          // 4608 u32
#define QKV_SMEM_BYTES ((QA_SZ + 3 * QB_SZ) * 4)   // 90112 B

__global__ void __launch_bounds__(256, 2) gemm_qkv(const __half* __restrict__ A,
                                                   const __half* __restrict__ Bt,
                                                   uint32_t* __restrict__ O32) {
    extern __shared__ uint32_t sg[];
    const uint32_t sb = smem_u32(sg);
    const int tid = threadIdx.x;
    const int wid = tid >> 5, lane = tid & 31;
    const int wm = wid & 3, wn = wid >> 2;
    const int lg = lane >> 2, lc = lane & 3;
    const int m0 = blockIdx.x * 128;
    const int arow = lane & 15, acol = ((lane >> 4) & 1) * 4;
    const int krow = ((lane >> 4) & 1) * 8 + (lane & 7);
    const int kcol = ((lane >> 3) & 1) * 4;

    // G0: A tile (128x128 f16) + B chunk 0 (nb=0,kc=0)
    #pragma unroll
    for (int t = 0; t < 8; t++) {
        int idx = tid + t * 256;
        int r = idx >> 4, cc = idx & 15;
        cpa16(sb + (r * QA_ST + cc * 4) * 4, A + (size_t)(m0 + r) * 128 + cc * 8);
    }
    #pragma unroll
    for (int t = 0; t < 4; t++) {
        int idx = tid + t * 256;
        int r = idx >> 3, cc = idx & 7;
        cpa16(sb + (QA_SZ + r * QB_ST + cc * 4) * 4,
              Bt + (size_t)r * 128 + cc * 8);
    }
    CP_COMMIT();
    // G1: B chunk 1 (nb=0,kc=1)
    #pragma unroll
    for (int t = 0; t < 4; t++) {
        int idx = tid + t * 256;
        int r = idx >> 3, cc = idx & 7;
        cpa16(sb + (QA_SZ + QB_SZ + r * QB_ST + cc * 4) * 4,
              Bt + (size_t)r * 128 + 64 + cc * 8);
    }
    CP_COMMIT();

    float acc[2][8][4];
    #pragma unroll
    for (int a = 0; a < 2; a++)
        #pragma unroll
        for (int b = 0; b < 8; b++)
            #pragma unroll
            for (int c = 0; c < 4; c++) acc[a][b][c] = 0.f;

    for (int j = 0; j < 12; j++) {
        if (j + 1 < 12) CP_WAIT1(); else CP_WAIT0();
        __syncthreads();
        if (j + 2 < 12) {
            const int nb2 = (j + 2) >> 1, kc2 = (j + 2) & 1;
            const uint32_t buf = QA_SZ + (uint32_t)((j + 2) % 3) * QB_SZ;
            #pragma unroll
            for (int t = 0; t < 4; t++) {
                int idx = tid + t * 256;
                int r = idx >> 3, cc = idx & 7;
                cpa16(sb + (buf + r * QB_ST + cc * 4) * 4,
                      Bt + (size_t)(nb2 * 128 + r) * 128 + kc2 * 64 + cc * 8);
            }
            CP_COMMIT();
        }
        const uint32_t bbase = sb + (QA_SZ + (uint32_t)(j % 3) * QB_SZ) * 4;
        const int kc = j & 1;
        #pragma unroll
        for (int s = 0; s < 4; s++) {
            const int ka = kc * 32 + s * 8;
            uint32_t af[2][4];
            #pragma unroll
            for (int tm = 0; tm < 2; tm++)
                ldmx4(af[tm][0], af[tm][1], af[tm][2], af[tm][3],
                      sb + ((wm * 32 + tm * 16 + arow) * QA_ST + ka + acol) * 4);
            #pragma unroll
            for (int tn2 = 0; tn2 < 4; tn2++) {
                uint32_t b0, b1, b2, b3;
                ldmx4(b0, b1, b2, b3,
                      bbase + ((wn * 64 + 16 * tn2 + krow) * QB_ST + s * 8 + kcol) * 4);
                mma_f16(acc[0][2 * tn2],     af[0], b0, b1);
                mma_f16(acc[0][2 * tn2 + 1], af[0], b2, b3);
                mma_f16(acc[1][2 * tn2],     af[1], b0, b1);
                mma_f16(acc[1][2 * tn2 + 1], af[1], b2, b3);
            }
        }
        if (kc == 1) {
            const int n0 = (j >> 1) * 128;
            #pragma unroll
            for (int tm = 0; tm < 2; tm++) {
                const int r = m0 + wm * 32 + tm * 16 + lg;
                #pragma unroll
                for (int tn = 0; tn < 8; tn++) {
                    const int cc = n0 + wn * 64 + tn * 8 + 2 * lc;
                    const float s = (cc < 256) ? SCL : 1.f;
                    stcs32(&O32[(size_t)r * 384 + (cc >> 1)],
                           pack_h2(acc[tm][tn][0] * s, acc[tm][tn][1] * s));
                    stcs32(&O32[(size_t)(r + 8) * 384 + (cc >> 1)],
                           pack_h2(acc[tm][tn][2] * s, acc[tm][tn][3] * s));
                    acc[tm][tn][0] = 0.f; acc[tm][tn][1] = 0.f;
                    acc[tm][tn][2] = 0.f; acc[tm][tn][3] = 0.f;
                }
            }
        }
    }
}

// ================== out-proj GEMM, 3-stage, ldmatrix frags =====================
#define G_ST  20
#define G_BUF (128 * G_ST)
#define GEMM_SMEM_BYTES (6 * G_BUF * 4)

__global__ void __launch_bounds__(256, 2) gemm_out(const __half* __restrict__ A,
                                                   const __half* __restrict__ Bt,
                                                   const float* __restrict__ bias,
                                                   float* __restrict__ C) {
    extern __shared__ uint32_t sg[];
    const uint32_t sb = smem_u32(sg);
    const int tid = threadIdx.x;
    const int wid = tid >> 5, lane = tid & 31;
    const int wm = wid & 3, wn = wid >> 2;
    const int lg = lane >> 2, lc = lane & 3;
    const int m0 = blockIdx.y * 128;
    const int Ktot = 256, Ntot = 128;
    const int nt = 8;
    const int arow = lane & 15, acol = ((lane >> 4) & 1) * 4;
    const int krow = ((lane >> 4) & 1) * 8 + (lane & 7);
    const int kcol = ((lane >> 3) & 1) * 4;

    float acc[2][8][4];
    #pragma unroll
    for (int a = 0; a < 2; a++)
        #pragma unroll
        for (int b = 0; b < 8; b++)
            #pragma unroll
            for (int c = 0; c < 4; c++) acc[a][b][c] = 0.f;

    #pragma unroll
    for (int st = 0; st < 2; st++) {
        const int kt = st * 32;
        #pragma unroll
        for (int t = 0; t < 2; t++) {
            int idx = tid + t * 256;
            int r = idx >> 2, cc = idx & 3;
            cpa16(sb + ((uint32_t)st * G_BUF + r * G_ST + cc * 4) * 4,
                  A + (size_t)(m0 + r) * Ktot + kt + cc * 8);
        }
        #pragma unroll
        for (int t = 0; t < 2; t++) {
            int idx = tid + t * 256;
            int r = idx >> 2, cc = idx & 3;
            cpa16(sb + ((uint32_t)(3 + st) * G_BUF + r * G_ST + cc * 4) * 4,
                  Bt + (size_t)r * Ktot + kt + cc * 8);
        }
        CP_COMMIT();
    }

    for (int j = 0; j < nt; j++) {
        if (j + 1 < nt) CP_WAIT1(); else CP_WAIT0();
        __syncthreads();
        if (j + 2 < nt) {
            const int st = (j + 2) % 3;
            const int kt = (j + 2) << 5;
            #pragma unroll
            for (int t = 0; t < 2; t++) {
                int idx = tid + t * 256;
                int r = idx >> 2, cc = idx & 3;
                cpa16(sb + ((uint32_t)st * G_BUF + r * G_ST + cc * 4) * 4,
                      A + (size_t)(m0 + r) * Ktot + kt + cc * 8);
            }
            #pragma unroll
            for (int t = 0; t < 2; t++) {
                int idx = tid + t * 256;
                int r = idx >> 2, cc = idx & 3;
                cpa16(sb + ((uint32_t)(3 + st) * G_BUF + r * G_ST + cc * 4) * 4,
                      Bt + (size_t)r * Ktot + kt + cc * 8);
            }
            CP_COMMIT();
        }
        const uint32_t abase = sb + (uint32_t)(j % 3) * G_BUF * 4;
        const uint32_t bbase = sb + (uint32_t)(3 + (j % 3)) * G_BUF * 4;
        #pragma unroll
        for (int s = 0; s < 2; s++) {
            uint32_t af[2][4];
            #pragma unroll
            for (int tm = 0; tm < 2; tm++)
                ldmx4(af[tm][0], af[tm][1], af[tm][2], af[tm][3],
                      abase + ((wm * 32 + tm * 16 + arow) * G_ST + s * 8 + acol) * 4);
            #pragma unroll
            for (int tn2 = 0; tn2 < 4; tn2++) {
                uint32_t b0, b1, b2, b3;
                ldmx4(b0, b1, b2, b3,
                      bbase + ((wn * 64 + 16 * tn2 + krow) * G_ST + s * 8 + kcol) * 4);
                mma_f16(acc[0][2 * tn2],     af[0], b0, b1);
                mma_f16(acc[0][2 * tn2 + 1], af[0], b2, b3);
                mma_f16(acc[1][2 * tn2],     af[1], b0, b1);
                mma_f16(acc[1][2 * tn2 + 1], af[1], b2, b3);
            }
        }
    }
    #pragma unroll
    for (int tm = 0; tm < 2; tm++) {
        const int r = m0 + wm * 32 + tm * 16 + lg;
        #pragma unroll
        for (int tn = 0; tn < 8; tn++) {
            const int cc = wn * 64 + tn * 8 + 2 * lc;
            const float bx = bias[cc], by = bias[cc + 1];
            stcs_f2(&C[(size_t)r * Ntot + cc],
                    make_float2(acc[tm][tn][0] + bx, acc[tm][tn][1] + by));
            stcs_f2(&C[(size_t)(r + 8) * Ntot + cc],
                    make_float2(acc[tm][tn][2] + bx, acc[tm][tn][3] + by));
        }
    }
}

// ================== all-f16 flash attention (R14-exact): 3-stage K/V ==========
#define T_ST  36
#define T_BUF (64 * T_ST)
#define OFF_K  0
#define OFF_V  (3 * T_BUF)
#define ATTN_SMEM_BYTES (6 * T_BUF * 4)   // 55296 B

__global__ void __launch_bounds__(64, 4) attn_flash(const __half* __restrict__ qkv,
                                                    const uint32_t* __restrict__ bias16,
                                                    uint32_t* __restrict__ ao32) {
    extern __shared__ uint32_t smu[];
    const uint32_t sbm = smem_u32(smu);

    const int qt = blockIdx.x, h = blockIdx.y, i = blockIdx.z;
    const int tid = threadIdx.x;
    const int w = tid >> 5, lane = tid & 31;
    const int lg = lane >> 2, lc = lane & 3;
    const int qg0 = qt * 64;
    const int qr0 = w * 32;
    const size_t rowbase = (size_t)i * NSEQ;

    const int krow = ((lane >> 4) & 1) * 8 + (lane & 7);
    const int kcol = ((lane >> 3) & 1) * 4;
    const int vrow = ((lane >> 3) & 1) * 8 + (lane & 7);
    const int vcol = ((lane >> 4) & 1) * 4;

    const uint32_t QSTAGE = OFF_K + 2 * T_BUF;
    #pragma unroll
    for (int t = 0; t < 8; t++) {
        int idx = tid + t * 64;
        int r = idx >> 3, cc = idx & 7;
        cpa16(sbm + (QSTAGE + r * T_ST + cc * 4) * 4,
              qkv + (rowbase + qg0 + r) * 768 + h * 64 + cc * 8);
    }
    CP_COMMIT();
    #pragma unroll
    for (int c = 0; c < 2; c++) {
        #pragma unroll
        for (int t = 0; t < 8; t++) {
            int idx = tid + t * 64;
            int r = idx >> 3, cc = idx & 7;
            cpa16(sbm + (OFF_K + c * T_BUF + r * T_ST + cc * 4) * 4,
                  qkv + (rowbase + c * 64 + r) * 768 + 256 + h * 64 + cc * 8);
        }
        #pragma unroll
        for (int t = 0; t < 8; t++) {
            int idx = tid + t * 64;
            int r = idx >> 3, cc = idx & 7;
            cpa16(sbm + (OFF_V + c * T_BUF + r * T_ST + cc * 4) * 4,
                  qkv + (rowbase + c * 64 + r) * 768 + 512 + h * 64 + cc * 8);
        }
        CP_COMMIT();
    }

    CP_WAIT2();
    __syncthreads();
    const uint32_t* Qst = smu + QSTAGE;
    uint32_t qa[2][4][4];
    #pragma unroll
    for (int mt = 0; mt < 2; mt++) {
        const int qr = qr0 + mt * 16 + lg;
        #pragma unroll
        for (int s = 0; s < 4; s++) {
            qa[mt][s][0] = Qst[qr * T_ST + s * 8 + lc];
            qa[mt][s][1] = Qst[(qr + 8) * T_ST + s * 8 + lc];
            qa[mt][s][2] = Qst[qr * T_ST + s * 8 + lc + 4];
            qa[mt][s][3] = Qst[(qr + 8) * T_ST + s * 8 + lc + 4];
        }
    }

    float oacc[2][8][4];
    #pragma unroll
    for (int mt = 0; mt < 2; mt++)
        #pragma unroll
        for (int a = 0; a < 8; a++)
            #pragma unroll
            for (int b = 0; b < 4; b++) oacc[mt][a][b] = 0.f;
    float ls[2][2] = {{0.f, 0.f}, {0.f, 0.f}};

    for (int kc = 0; kc < 5; kc++) {
        if (kc == 4) CP_WAIT0(); else CP_WAIT1();
        __syncthreads();

        if (kc < 3) {
            const int nb = (kc + 2) % 3;
            const size_t src = rowbase + (size_t)(kc + 2) * 64;
            #pragma unroll
            for (int t = 0; t < 8; t++) {
                int idx = tid + t * 64;
                int r = idx >> 3, cc = idx & 7;
                cpa16(sbm + (OFF_K + nb * T_BUF + r * T_ST + cc * 4) * 4,
                      qkv + (src + r) * 768 + 256 + h * 64 + cc * 8);
            }
            #pragma unroll
            for (int t = 0; t < 8; t++) {
                int idx = tid + t * 64;
                int r = idx >> 3, cc = idx & 7;
                cpa16(sbm + (OFF_V + nb * T_BUF + r * T_ST + cc * 4) * 4,
                      qkv + (src + r) * 768 + 512 + h * 64 + cc * 8);
            }
            CP_COMMIT();
        }

        float sacc[2][8][4];
        #pragma unroll
        for (int mt = 0; mt < 2; mt++) {
            const uint32_t* bp = &bias16[((size_t)h * MROWS
                                  + (size_t)(qg0 + qr0 + mt * 16 + lg) * NSEQ
                                  + kc * 64) >> 1];
            #pragma unroll
            for (int tn = 0; tn < 8; tn++) {
                uint32_t u0 = bp[tn * 4 + lc];
                uint32_t u1 = bp[(8 * NSEQ >> 1) + tn * 4 + lc];
                float2 b0 = __half22float2(*(const __half2*)&u0);
                float2 b1 = __half22float2(*(const __half2*)&u1);
                sacc[mt][tn][0] = b0.x; sacc[mt][tn][1] = b0.y;
                sacc[mt][tn][2] = b1.x; sacc[mt][tn][3] = b1.y;
            }
        }

        const uint32_t kbase = sbm + (OFF_K + (kc % 3) * T_BUF) * 4;
        #pragma unroll
        for (int s = 0; s < 4; s++) {
            #pragma unroll
            for (int tn2 = 0; tn2 < 4; tn2++) {
                uint32_t b0, b1, b2, b3;
                ldmx4(b0, b1, b2, b3,
                      kbase + ((16 * tn2 + krow) * T_ST + 8 * s + kcol) * 4);
                mma_f16(sacc[0][2 * tn2],     qa[0][s], b0, b1);
                mma_f16(sacc[0][2 * tn2 + 1], qa[0][s], b2, b3);
                mma_f16(sacc[1][2 * tn2],     qa[1][s], b0, b1);
                mma_f16(sacc[1][2 * tn2 + 1], qa[1][s], b2, b3);
            }
        }

        uint32_t ph[2][8][2];
        #pragma unroll
        for (int mt = 0; mt < 2; mt++) {
            #pragma unroll
            for (int tn = 0; tn < 8; tn++) {
                float p0 = ex2f(sacc[mt][tn][0]);
                float p1 = ex2f(sacc[mt][tn][1]);
                float p2 = ex2f(sacc[mt][tn][2]);
                float p3 = ex2f(sacc[mt][tn][3]);
                ls[mt][0] += p0 + p1; ls[mt][1] += p2 + p3;
                ph[mt][tn][0] = pack_h2(p0, p1);
                ph[mt][tn][1] = pack_h2(p2, p3);
            }
        }

        const uint32_t vbase = sbm + (OFF_V + (kc % 3) * T_BUF) * 4;
        #pragma unroll
        for (int jt = 0; jt < 4; jt++) {
            uint32_t af0[4], af1[4];
            af0[0] = ph[0][2 * jt][0]; af0[1] = ph[0][2 * jt][1];
            af0[2] = ph[0][2 * jt + 1][0]; af0[3] = ph[0][2 * jt + 1][1];
            af1[0] = ph[1][2 * jt][0]; af1[1] = ph[1][2 * jt][1];
            af1[2] = ph[1][2 * jt + 1][0]; af1[3] = ph[1][2 * jt + 1][1];
            #pragma unroll
            for (int tn2 = 0; tn2 < 4; tn2++) {
                uint32_t b0, b1, b2, b3;
                ldmx4t(b0, b1, b2, b3,
                       vbase + ((16 * jt + vrow) * T_ST + 8 * tn2 + vcol) * 4);
                mma_f16(oacc[0][2 * tn2],     af0, b0, b1);
                mma_f16(oacc[0][2 * tn2 + 1], af0, b2, b3);
                mma_f16(oacc[1][2 * tn2],     af1, b0, b1);
                mma_f16(oacc[1][2 * tn2 + 1], af1, b2, b3);
            }
        }
    }

    #pragma unroll
    for (int mt = 0; mt < 2; mt++) {
        ls[mt][0] += __shfl_xor_sync(0xffffffffu, ls[mt][0], 1);
        ls[mt][0] += __shfl_xor_sync(0xffffffffu, ls[mt][0], 2);
        ls[mt][1] += __shfl_xor_sync(0xffffffffu, ls[mt][1], 1);
        ls[mt][1] += __shfl_xor_sync(0xffffffffu, ls[mt][1], 2);
        const float i0 = 1.f / ls[mt][0], i1 = 1.f / ls[mt][1];
        const int qr = qg0 + qr0 + mt * 16 + lg;
        #pragma unroll
        for (int tn = 0; tn < 8; tn++) {
            const int col = h * 64 + tn * 8 + 2 * lc;
            stcs32(&ao32[(rowbase + qr) * 128 + (col >> 1)],
                   pack_h2(oacc[mt][tn][0] * i0, oacc[mt][tn][1] * i0));
            stcs32(&ao32[(rowbase + qr + 8) * 128 + (col >> 1)],
                   pack_h2(oacc[mt][tn][2] * i1, oacc[mt][tn][3] * i1));
        }
    }
}

// ---------------- launch ------------------------------------------------------
extern "C" void kernel_launch(void* const* d_in, const int* in_sizes, int n_in,
                              void* d_out, int out_size) {
    const float* pw    = (const float*)d_in[0];
    const float* Wqkv  = (const float*)d_in[1];
    const float* Wout  = (const float*)d_in[2];
    const float* bout  = (const float*)d_in[3];
    const float* Wbias = (const float*)d_in[4];
    float* out = (float*)d_out;

    __half *pwh, *qkvh, *ao, *wqt, *wot, *biash;
    cudaGetSymbolAddress((void**)&pwh, g_pwh);
    cudaGetSymbolAddress((void**)&qkvh, g_qkvh);
    cudaGetSymbolAddress((void**)&ao, g_ao);
    cudaGetSymbolAddress((void**)&wqt, g_wqt);
    cudaGetSymbolAddress((void**)&wot, g_wot);
    cudaGetSymbolAddress((void**)&biash, g_biash);

    cudaFuncSetAttribute(gemm_qkv,
                         cudaFuncAttributeMaxDynamicSharedMemorySize, QKV_SMEM_BYTES);
    cudaFuncSetAttribute(gemm_out,
                         cudaFuncAttributeMaxDynamicSharedMemorySize, GEMM_SMEM_BYTES);
    cudaFuncSetAttribute(attn_flash,
                         cudaFuncAttributeMaxDynamicSharedMemorySize, ATTN_SMEM_BYTES);

    // 0) weights -> transposed f16
    prep_wt<<<384, 256>>>(Wqkv, Wout, wqt, wot);
    // 1) fused: pw -> f16 + pair bias (f16 direct)
    prep_bias<<<MROWS / 8, 256>>>(pw, Wbias, (uint32_t*)pwh, biash);
    // 2) persistent-A qkv projection (BK=64, 3-stage, ldmatrix)
    gemm_qkv<<<800, 256, QKV_SMEM_BYTES>>>(pwh, wqt, (uint32_t*)qkvh);
    // 3) all-f16 flash attention (R14-exact)
    attn_flash<<<dim3(5, HEADS, NSEQ), 64, ATTN_SMEM_BYTES>>>(
        qkvh, (const uint32_t*)biash, (uint32_t*)ao);
    // 4) out = attnout @ Wout + bout (3-stage, ldmatrix)
    gemm_out<<<dim3(1, MROWS / 128), 256, GEMM_SMEM_BYTES>>>(ao, wot, bout, out);
}